// round 14
// baseline (speedup 1.0000x reference)
#include <cuda_runtime.h>
#include <stdint.h>
#include <math.h>

// ---------------------------------------------------------------------------
// out[b,o] = min_i ( x[b,i] + mask[o,i] ),  B=IN=OUT=512,  x in [0,1)
// mask in {0,1}  =>  out[b,o] = min over SELECTED i of x[b,i]  (sparse min).
// Selection = JAX threefry bernoulli (partitionable variant, validated R2-R13).
// One persistent kernel: warp 0 filter+sort candidates (x < TAU), warps 1-7
// threefry mask -> grid barrier -> staged butterfly gather + exact fallback.
// ---------------------------------------------------------------------------

#define B_DIM   512
#define IN_DIM  512
#define OUT_DIM 512
#define NBLK    512u
#define TAU     0.15f

// ROW-major selection bitmask: bit o%32 of g_sel[i*16 + (o>>5)]
__device__ uint32_t g_sel[IN_DIM * 16];
__device__ unsigned g_bar;        // monotonic epoch counter (never reset)

// ---------------- Threefry-2x32 (constexpr) --------------------------------
struct TF2 { uint32_t a, b; };

__host__ __device__ constexpr uint32_t rotl32(uint32_t v, int r) {
    return (v << r) | (v >> (32 - r));
}

__host__ __device__ constexpr TF2 tf2x32(uint32_t k0, uint32_t k1,
                                         uint32_t x0, uint32_t x1) {
    uint32_t k2 = k0 ^ k1 ^ 0x1BD11BDAu;
    x0 += k0; x1 += k1;
    x0 += x1; x1 = rotl32(x1, 13) ^ x0;
    x0 += x1; x1 = rotl32(x1, 15) ^ x0;
    x0 += x1; x1 = rotl32(x1, 26) ^ x0;
    x0 += x1; x1 = rotl32(x1,  6) ^ x0;
    x0 += k1; x1 += k2 + 1u;
    x0 += x1; x1 = rotl32(x1, 17) ^ x0;
    x0 += x1; x1 = rotl32(x1, 29) ^ x0;
    x0 += x1; x1 = rotl32(x1, 16) ^ x0;
    x0 += x1; x1 = rotl32(x1, 24) ^ x0;
    x0 += k2; x1 += k0 + 2u;
    x0 += x1; x1 = rotl32(x1, 13) ^ x0;
    x0 += x1; x1 = rotl32(x1, 15) ^ x0;
    x0 += x1; x1 = rotl32(x1, 26) ^ x0;
    x0 += x1; x1 = rotl32(x1,  6) ^ x0;
    x0 += k0; x1 += k1 + 3u;
    x0 += x1; x1 = rotl32(x1, 17) ^ x0;
    x0 += x1; x1 = rotl32(x1, 29) ^ x0;
    x0 += x1; x1 = rotl32(x1, 16) ^ x0;
    x0 += x1; x1 = rotl32(x1, 24) ^ x0;
    x0 += k1; x1 += k2 + 4u;
    x0 += x1; x1 = rotl32(x1, 13) ^ x0;
    x0 += x1; x1 = rotl32(x1, 15) ^ x0;
    x0 += x1; x1 = rotl32(x1, 26) ^ x0;
    x0 += x1; x1 = rotl32(x1,  6) ^ x0;
    x0 += k2; x1 += k0 + 5u;
    return TF2{x0, x1};
}

constexpr TF2 KB = tf2x32(0u, 42u, 0u, 0u);   // k_bern (foldlike split of key 42)

// ---------------- in-warp bitonic helpers (4 elems/lane, e = 4*lane+c) ------
#define BSWAP(A, PA, KEEPMIN) ((KEEPMIN) ? umin((A),(PA)) : umax((A),(PA)))

#define CE(A, B, ASC) { uint32_t lo_ = umin(A,B), hi_ = umax(A,B);            \
                        A = (ASC) ? lo_ : hi_;  B = (ASC) ? hi_ : lo_; }

#define INTRA(D) { CE(v0, v2, D) CE(v1, v3, D) CE(v0, v1, D) CE(v2, v3, D) }

#define SSTAGE(J4, D) {                                                       \
    uint32_t p0_ = __shfl_xor_sync(0xFFFFFFFFu, v0, J4);                      \
    uint32_t p1_ = __shfl_xor_sync(0xFFFFFFFFu, v1, J4);                      \
    uint32_t p2_ = __shfl_xor_sync(0xFFFFFFFFu, v2, J4);                      \
    uint32_t p3_ = __shfl_xor_sync(0xFFFFFFFFu, v3, J4);                      \
    bool km_ = (D) == ((lane & (J4)) == 0);                                   \
    v0 = BSWAP(v0, p0_, km_); v1 = BSWAP(v1, p1_, km_);                       \
    v2 = BSWAP(v2, p2_, km_); v3 = BSWAP(v3, p3_, km_); }

// 5-step butterfly 32x32 bit-matrix transpose across lanes
#define TSTEP(V, K, M) {                                                      \
    uint32_t y_ = __shfl_xor_sync(0xFFFFFFFFu, V, K);                         \
    V = (lane & (K)) ? ((V & (M)) | ((y_ >> (K)) & ~(M)))                     \
                     : ((V & ~(M)) | ((y_ << (K)) & (M))); }

#define TRANSPOSE32(V) TSTEP(V, 16, 0xFFFF0000u) TSTEP(V, 8, 0xFF00FF00u)     \
                       TSTEP(V, 4,  0xF0F0F0F0u) TSTEP(V, 2, 0xCCCCCCCCu)     \
                       TSTEP(V, 1,  0xAAAAAAAAu)

#define NBAR224() asm volatile("bar.sync 2, 224;" ::: "memory")

// ---------------- fused persistent kernel -----------------------------------
__global__ __launch_bounds__(256, 4) void fused_kernel(
    const float* __restrict__ x, const float* __restrict__ pw,
    float* __restrict__ out) {
    __shared__ uint32_t sk[128];                      // candidate keys
    __shared__ float    s_xv[512];
    __shared__ uint32_t s_ti[64];
    __shared__ float    s_tv[64];
    __shared__ int      s_L;                          // usable candidates (<=64)
    __shared__ float    s_wx[32][17], s_wy[32][17];   // padded pw stage
    __shared__ uint32_t s_m[64][17];                  // staged sel words
    __shared__ unsigned s_tgt;

    const int t    = threadIdx.x;
    const int bid  = blockIdx.x;
    const int lane = t & 31;
    const uint32_t wrp = (uint32_t)t >> 5;

    if (wrp == 0) {
        // ==== warp 0: load row, filter x < TAU, compact, sort 128 in-warp ===
        float4 xv4[4];
#pragma unroll
        for (int c = 0; c < 4; ++c) {
            xv4[c] = reinterpret_cast<const float4*>(x + bid * IN_DIM)[c * 32 + lane];
            reinterpret_cast<float4*>(s_xv)[c * 32 + lane] = xv4[c];
        }
        int base = 0;
#pragma unroll
        for (int c = 0; c < 4; ++c) {
            float vals[4] = {xv4[c].x, xv4[c].y, xv4[c].z, xv4[c].w};
#pragma unroll
            for (int q = 0; q < 4; ++q) {
                int idx = (c * 32 + lane) * 4 + q;
                bool p = vals[q] < TAU;
                uint32_t bal = __ballot_sync(0xFFFFFFFFu, p);
                int pos = base + __popc(bal & ((1u << lane) - 1u));
                if (p && pos < 128)
                    sk[pos] = ((__float_as_uint(vals[q]) >> 7) << 9) | (uint32_t)idx;
                base += __popc(bal);
            }
        }
        for (int j = base + lane; j < 128; j += 32) sk[j] = 0xFFFFFFFFu;
        __syncwarp();

        uint32_t v0 = sk[4*lane+0], v1 = sk[4*lane+1],
                 v2 = sk[4*lane+2], v3 = sk[4*lane+3];
        // in-warp bitonic sort of 128 (e = 4*lane + c)
        CE(v0, v1, true) CE(v2, v3, false)                        // k=2
        { bool d = ((lane & 1) == 0); INTRA(d) }                  // k=4
        { bool d = ((lane & 2) == 0); SSTAGE(1, d) INTRA(d) }     // k=8
        { bool d = ((lane & 4) == 0); SSTAGE(2, d) SSTAGE(1, d) INTRA(d) }
        { bool d = ((lane & 8) == 0);
          SSTAGE(4, d) SSTAGE(2, d) SSTAGE(1, d) INTRA(d) }
        { bool d = ((lane & 16) == 0);
          SSTAGE(8, d) SSTAGE(4, d) SSTAGE(2, d) SSTAGE(1, d) INTRA(d) }
        { const bool d = true;                                    // k=128
          SSTAGE(16, d) SSTAGE(8, d) SSTAGE(4, d) SSTAGE(2, d) SSTAGE(1, d) INTRA(d) }

        if (lane < 16) {                    // sorted elems 0..63
            uint32_t kk[4] = {v0, v1, v2, v3};
#pragma unroll
            for (int c = 0; c < 4; ++c) {
                uint32_t ii = kk[c] & 511u;
                s_ti[4*lane + c] = ii;
                s_tv[4*lane + c] = s_xv[ii];
            }
        }
        if (lane == 0) s_L = (base > 128) ? 0 : (base < 64 ? base : 64);
    } else {
        // ==== warps 1-7: threefry mask for (ow = bid&15, i in [ib,ib+16)) ===
        const uint32_t ow = (uint32_t)bid & 15u;
        const uint32_t ib = ((uint32_t)bid >> 4) * 16u;
        const int ts = t - 32;                        // 0..223

        // stage 32o x 16i pw block (4KB), contiguous loads
        const float2* pwp = reinterpret_cast<const float2*>(pw);
#pragma unroll
        for (int q = 0; q < 3; ++q) {
            int idx = q * 224 + ts;
            if (idx < 512) {
                int ol = idx >> 4, ii = idx & 15;
                float2 v = pwp[(ow * 32u + ol) * 512u + ib + ii];
                s_wx[ol][ii] = v.x;
                s_wy[ol][ii] = v.y;
            }
        }
        NBAR224();

        const uint32_t o = ow * 32u + lane;
        const int nc = (wrp <= 2) ? 3 : 2;            // warps 1,2: 3 chains
        uint32_t ll[3] = {wrp - 1u, wrp + 6u, wrp + 13u};
#pragma unroll
        for (int k = 0; k < 3; ++k) {
            if (k >= nc) break;
            uint32_t l = ll[k];
            uint32_t n = o * 512u + ib + l;
            TF2 r = tf2x32(KB.a, KB.b, 0u, n);
            uint32_t bits = r.a ^ r.b;
            float u = __uint_as_float((bits >> 9) | 0x3F800000u) - 1.0f;
            float wx = s_wx[lane][l], wy = s_wy[lane][l];
            float tt = u * (1.0f + __expf(wx - wy));
            bool s;
            if (tt < 1.0f - 1e-5f)      s = true;
            else if (tt > 1.0f + 1e-5f) s = false;
            else {                                    // boundary: exact fp64
                double e = exp((double)wx - (double)wy);
                s = ((double)u) * (1.0 + e) < 1.0;
            }
            uint32_t word = __ballot_sync(0xFFFFFFFFu, s);
            if (lane == 0) g_sel[(ib + l) * 16u + ow] = word;
        }
    }

    // ======== grid barrier (all co-resident: 512 blocks <= 148*4) ===========
    __syncthreads();
    if (t == 0) {
        __threadfence();
        unsigned arr = atomicAdd(&g_bar, 1u);
        s_tgt = (arr / NBLK + 1u) * NBLK;
    }
    __syncthreads();
    if (t == 0) {
        unsigned tgt = s_tgt, v;
        for (;;) {
            asm volatile("ld.global.acquire.gpu.u32 %0, [%1];"
                         : "=r"(v) : "l"(&g_bar));
            if (v >= tgt) break;
            __nanosleep(64);
        }
    }
    __syncthreads();

    // ======== Phase C: staged gather for b = bid ============================
    const int L = s_L;
#pragma unroll
    for (int q = 0; q < 4; ++q) {
        int idx = q * 256 + t;                        // 0..1023
        int j = idx >> 4, ow2 = idx & 15;
        s_m[j][ow2] = (j < L) ? g_sel[s_ti[j] * 16u + ow2] : 0u;
    }
    __syncthreads();

    {
        const uint32_t ow0 = wrp, ow1 = wrp + 8u;
        float val = s_tv[lane];
        uint32_t m0 = s_m[lane][ow0];                 // conflict-free (pad 17)
        uint32_t m1 = s_m[lane][ow1];
        TRANSPOSE32(m0)
        TRANSPOSE32(m1)
        bool ok0 = (m0 != 0), ok1 = (m1 != 0);
        float r0 = __shfl_sync(0xFFFFFFFFu, val, ok0 ? (__ffs(m0) - 1) : 0);
        float r1 = __shfl_sync(0xFFFFFFFFu, val, ok1 ? (__ffs(m1) - 1) : 0);

        if (!__all_sync(0xFFFFFFFFu, ok0 && ok1)) {   // rare second round
            float val2 = s_tv[32 + lane];
            uint32_t n0 = s_m[32 + lane][ow0];
            uint32_t n1 = s_m[32 + lane][ow1];
            TRANSPOSE32(n0)
            TRANSPOSE32(n1)
            float q0 = __shfl_sync(0xFFFFFFFFu, val2, n0 ? (__ffs(n0) - 1) : 0);
            float q1 = __shfl_sync(0xFFFFFFFFu, val2, n1 ? (__ffs(n1) - 1) : 0);
            if (!ok0 && n0) { r0 = q0; ok0 = true; }
            if (!ok1 && n1) { r1 = q1; ok1 = true; }

            if (!ok0 || !ok1) {                       // exact dense fallback
                float b0 = INFINITY, b1 = INFINITY, ball = INFINITY;
                for (int i = 0; i < IN_DIM; ++i) {
                    float v = s_xv[i];
                    ball = fminf(ball, v);
                    if ((g_sel[i * 16u + ow0] >> lane) & 1u) b0 = fminf(b0, v);
                    if ((g_sel[i * 16u + ow1] >> lane) & 1u) b1 = fminf(b1, v);
                }
                if (!ok0) r0 = isinf(b0) ? ball + 1.0f : b0;
                if (!ok1) r1 = isinf(b1) ? ball + 1.0f : b1;
            }
        }

        out[bid * OUT_DIM + ow0 * 32u + lane] = r0;   // coalesced
        out[bid * OUT_DIM + ow1 * 32u + lane] = r1;
    }
}

// ---------------------------------------------------------------------------
extern "C" void kernel_launch(void* const* d_in, const int* in_sizes, int n_in,
                              void* d_out, int out_size) {
    const float* x  = (const float*)d_in[0];   // [512, 512]
    const float* pw = (const float*)d_in[1];   // [512, 512, 2]
    float* out      = (float*)d_out;           // [512, 512]

    fused_kernel<<<NBLK, 256>>>(x, pw, out);
}

// round 15
// speedup vs baseline: 1.0208x; 1.0208x over previous
#include <cuda_runtime.h>
#include <stdint.h>
#include <math.h>

// ---------------------------------------------------------------------------
// out[b,o] = min_i ( x[b,i] + mask[o,i] ),  B=IN=OUT=512,  x in [0,1)
// mask in {0,1}  =>  out[b,o] = min over SELECTED i of x[b,i]  (sparse min).
// Selection = JAX threefry bernoulli (partitionable variant, validated R2-R14).
// K1: mask (coalesced, ILP4).  K2: per-row filter+sort+butterfly gather.
// ---------------------------------------------------------------------------

#define B_DIM   512
#define IN_DIM  512
#define OUT_DIM 512
#define TAU     0.15f

// ROW-major selection bitmask: bit o%32 of g_sel[i*16 + (o>>5)]
__device__ uint32_t g_sel[IN_DIM * 16];

// ---------------- Threefry-2x32 (constexpr) --------------------------------
struct TF2 { uint32_t a, b; };

__host__ __device__ constexpr uint32_t rotl32(uint32_t v, int r) {
    return (v << r) | (v >> (32 - r));
}

__host__ __device__ constexpr TF2 tf2x32(uint32_t k0, uint32_t k1,
                                         uint32_t x0, uint32_t x1) {
    uint32_t k2 = k0 ^ k1 ^ 0x1BD11BDAu;
    x0 += k0; x1 += k1;
    x0 += x1; x1 = rotl32(x1, 13) ^ x0;
    x0 += x1; x1 = rotl32(x1, 15) ^ x0;
    x0 += x1; x1 = rotl32(x1, 26) ^ x0;
    x0 += x1; x1 = rotl32(x1,  6) ^ x0;
    x0 += k1; x1 += k2 + 1u;
    x0 += x1; x1 = rotl32(x1, 17) ^ x0;
    x0 += x1; x1 = rotl32(x1, 29) ^ x0;
    x0 += x1; x1 = rotl32(x1, 16) ^ x0;
    x0 += x1; x1 = rotl32(x1, 24) ^ x0;
    x0 += k2; x1 += k0 + 2u;
    x0 += x1; x1 = rotl32(x1, 13) ^ x0;
    x0 += x1; x1 = rotl32(x1, 15) ^ x0;
    x0 += x1; x1 = rotl32(x1, 26) ^ x0;
    x0 += x1; x1 = rotl32(x1,  6) ^ x0;
    x0 += k0; x1 += k1 + 3u;
    x0 += x1; x1 = rotl32(x1, 17) ^ x0;
    x0 += x1; x1 = rotl32(x1, 29) ^ x0;
    x0 += x1; x1 = rotl32(x1, 16) ^ x0;
    x0 += x1; x1 = rotl32(x1, 24) ^ x0;
    x0 += k1; x1 += k2 + 4u;
    x0 += x1; x1 = rotl32(x1, 13) ^ x0;
    x0 += x1; x1 = rotl32(x1, 15) ^ x0;
    x0 += x1; x1 = rotl32(x1, 26) ^ x0;
    x0 += x1; x1 = rotl32(x1,  6) ^ x0;
    x0 += k2; x1 += k0 + 5u;
    return TF2{x0, x1};
}

constexpr TF2 KB = tf2x32(0u, 42u, 0u, 0u);   // k_bern (foldlike split of key 42)

// ---------------- in-warp bitonic helpers (4 elems/lane, e = 4*lane+c) ------
#define BSWAP(A, PA, KEEPMIN) ((KEEPMIN) ? umin((A),(PA)) : umax((A),(PA)))

#define CE(A, B, ASC) { uint32_t lo_ = umin(A,B), hi_ = umax(A,B);            \
                        A = (ASC) ? lo_ : hi_;  B = (ASC) ? hi_ : lo_; }

#define INTRA(D) { CE(v0, v2, D) CE(v1, v3, D) CE(v0, v1, D) CE(v2, v3, D) }

#define SSTAGE(J4, D) {                                                       \
    uint32_t p0_ = __shfl_xor_sync(0xFFFFFFFFu, v0, J4);                      \
    uint32_t p1_ = __shfl_xor_sync(0xFFFFFFFFu, v1, J4);                      \
    uint32_t p2_ = __shfl_xor_sync(0xFFFFFFFFu, v2, J4);                      \
    uint32_t p3_ = __shfl_xor_sync(0xFFFFFFFFu, v3, J4);                      \
    bool km_ = (D) == ((lane & (J4)) == 0);                                   \
    v0 = BSWAP(v0, p0_, km_); v1 = BSWAP(v1, p1_, km_);                       \
    v2 = BSWAP(v2, p2_, km_); v3 = BSWAP(v3, p3_, km_); }

// 5-step butterfly 32x32 bit-matrix transpose across lanes
#define TSTEP(V, K, M) {                                                      \
    uint32_t y_ = __shfl_xor_sync(0xFFFFFFFFu, V, K);                         \
    V = (lane & (K)) ? ((V & (M)) | ((y_ >> (K)) & ~(M)))                     \
                     : ((V & ~(M)) | ((y_ << (K)) & (M))); }

#define TRANSPOSE32(V) TSTEP(V, 16, 0xFFFF0000u) TSTEP(V, 8, 0xFF00FF00u)     \
                       TSTEP(V, 4,  0xF0F0F0F0u) TSTEP(V, 2, 0xCCCCCCCCu)     \
                       TSTEP(V, 1,  0xAAAAAAAAu)

// ---------------- K1: mask ---------------------------------------------------
// 256 CTAs: CTA = (ow = bid&15, ib = (bid>>4)*32). Staged pw, ILP4 threefry.
__global__ __launch_bounds__(256) void mask_kernel(const float* __restrict__ pw) {
    __shared__ float s_wx[32][33], s_wy[32][33];      // padded: conflict-free

    const int t    = threadIdx.x;
    const int lane = t & 31;
    const uint32_t w  = (uint32_t)t >> 5;             // 0..7
    const uint32_t ow = (uint32_t)blockIdx.x & 15u;
    const uint32_t ib = ((uint32_t)blockIdx.x >> 4) * 32u;

    // stage 32o x 32i pw block (8KB), 256B-contiguous per o-row
    const float2* pwp = reinterpret_cast<const float2*>(pw);
#pragma unroll
    for (int q = 0; q < 4; ++q) {
        int idx = q * 256 + t;                        // 0..1023
        int ol = idx >> 5, ii = idx & 31;
        float2 v = pwp[(ow * 32u + ol) * 512u + ib + ii];
        s_wx[ol][ii] = v.x;
        s_wy[ol][ii] = v.y;
    }
    __syncthreads();

    const uint32_t o = ow * 32u + lane;
    uint32_t iloc[4]; bool s[4];
#pragma unroll
    for (int k = 0; k < 4; ++k) {                     // 4 independent chains
        iloc[k] = w * 4u + k;
        uint32_t n = o * 512u + ib + iloc[k];
        TF2 r = tf2x32(KB.a, KB.b, 0u, n);
        uint32_t bits = r.a ^ r.b;
        float u = __uint_as_float((bits >> 9) | 0x3F800000u) - 1.0f;
        float wx = s_wx[lane][iloc[k]], wy = s_wy[lane][iloc[k]];
        float tt = u * (1.0f + __expf(wx - wy));
        if (tt < 1.0f - 1e-5f)      s[k] = true;
        else if (tt > 1.0f + 1e-5f) s[k] = false;
        else {                                        // boundary: exact fp64
            double e = exp((double)wx - (double)wy);
            s[k] = ((double)u) * (1.0 + e) < 1.0;
        }
    }
#pragma unroll
    for (int k = 0; k < 4; ++k) {
        uint32_t word = __ballot_sync(0xFFFFFFFFu, s[k]);
        if (lane == 0) g_sel[(ib + iloc[k]) * 16u + ow] = word;
    }
}

// ---------------- K2: per-row filter+sort + staged butterfly gather ---------
__global__ __launch_bounds__(256) void gather_kernel(
    const float* __restrict__ x, float* __restrict__ out) {
    __shared__ uint32_t sk[128];                      // candidate keys
    __shared__ float    s_xv[512];
    __shared__ uint32_t s_ti[64];
    __shared__ float    s_tv[64];
    __shared__ int      s_L;                          // usable candidates (<=64)
    __shared__ uint32_t s_m[64][17];                  // staged sel words

    const int t    = threadIdx.x;
    const int bid  = blockIdx.x;
    const int lane = t & 31;
    const uint32_t wrp = (uint32_t)t >> 5;

    if (wrp == 0) {
        // ==== warp 0: load row, filter x < TAU, compact, sort 128 in-warp ===
        float4 xv4[4];
#pragma unroll
        for (int c = 0; c < 4; ++c) {
            xv4[c] = reinterpret_cast<const float4*>(x + bid * IN_DIM)[c * 32 + lane];
            reinterpret_cast<float4*>(s_xv)[c * 32 + lane] = xv4[c];
        }
        int base = 0;
#pragma unroll
        for (int c = 0; c < 4; ++c) {
            float vals[4] = {xv4[c].x, xv4[c].y, xv4[c].z, xv4[c].w};
#pragma unroll
            for (int q = 0; q < 4; ++q) {
                int idx = (c * 32 + lane) * 4 + q;
                bool p = vals[q] < TAU;
                uint32_t bal = __ballot_sync(0xFFFFFFFFu, p);
                int pos = base + __popc(bal & ((1u << lane) - 1u));
                if (p && pos < 128)
                    sk[pos] = ((__float_as_uint(vals[q]) >> 7) << 9) | (uint32_t)idx;
                base += __popc(bal);
            }
        }
        for (int j = base + lane; j < 128; j += 32) sk[j] = 0xFFFFFFFFu;
        __syncwarp();

        uint32_t v0 = sk[4*lane+0], v1 = sk[4*lane+1],
                 v2 = sk[4*lane+2], v3 = sk[4*lane+3];
        // in-warp bitonic sort of 128 (e = 4*lane + c)
        CE(v0, v1, true) CE(v2, v3, false)                        // k=2
        { bool d = ((lane & 1) == 0); INTRA(d) }                  // k=4
        { bool d = ((lane & 2) == 0); SSTAGE(1, d) INTRA(d) }     // k=8
        { bool d = ((lane & 4) == 0); SSTAGE(2, d) SSTAGE(1, d) INTRA(d) }
        { bool d = ((lane & 8) == 0);
          SSTAGE(4, d) SSTAGE(2, d) SSTAGE(1, d) INTRA(d) }
        { bool d = ((lane & 16) == 0);
          SSTAGE(8, d) SSTAGE(4, d) SSTAGE(2, d) SSTAGE(1, d) INTRA(d) }
        { const bool d = true;                                    // k=128
          SSTAGE(16, d) SSTAGE(8, d) SSTAGE(4, d) SSTAGE(2, d) SSTAGE(1, d) INTRA(d) }

        if (lane < 16) {                    // sorted elems 0..63
            uint32_t kk[4] = {v0, v1, v2, v3};
#pragma unroll
            for (int c = 0; c < 4; ++c) {
                uint32_t ii = kk[c] & 511u;
                s_ti[4*lane + c] = ii;
                s_tv[4*lane + c] = s_xv[ii];
            }
        }
        if (lane == 0) s_L = (base > 128) ? 0 : (base < 64 ? base : 64);
    }
    __syncthreads();

    // stage sel words for 64 candidates x 16 ow (64B-contiguous loads)
    const int L = s_L;
#pragma unroll
    for (int q = 0; q < 4; ++q) {
        int idx = q * 256 + t;                        // 0..1023
        int j = idx >> 4, ow2 = idx & 15;
        s_m[j][ow2] = (j < L) ? g_sel[s_ti[j] * 16u + ow2] : 0u;
    }
    __syncthreads();

    {
        const uint32_t ow0 = wrp, ow1 = wrp + 8u;
        float val = s_tv[lane];
        uint32_t m0 = s_m[lane][ow0];                 // conflict-free (pad 17)
        uint32_t m1 = s_m[lane][ow1];
        TRANSPOSE32(m0)
        TRANSPOSE32(m1)
        bool ok0 = (m0 != 0), ok1 = (m1 != 0);
        float r0 = __shfl_sync(0xFFFFFFFFu, val, ok0 ? (__ffs(m0) - 1) : 0);
        float r1 = __shfl_sync(0xFFFFFFFFu, val, ok1 ? (__ffs(m1) - 1) : 0);

        if (!__all_sync(0xFFFFFFFFu, ok0 && ok1)) {   // rare second round
            float val2 = s_tv[32 + lane];
            uint32_t n0 = s_m[32 + lane][ow0];
            uint32_t n1 = s_m[32 + lane][ow1];
            TRANSPOSE32(n0)
            TRANSPOSE32(n1)
            float q0 = __shfl_sync(0xFFFFFFFFu, val2, n0 ? (__ffs(n0) - 1) : 0);
            float q1 = __shfl_sync(0xFFFFFFFFu, val2, n1 ? (__ffs(n1) - 1) : 0);
            if (!ok0 && n0) { r0 = q0; ok0 = true; }
            if (!ok1 && n1) { r1 = q1; ok1 = true; }

            if (!ok0 || !ok1) {                       // exact dense fallback
                float b0 = INFINITY, b1 = INFINITY, ball = INFINITY;
                for (int i = 0; i < IN_DIM; ++i) {
                    float v = s_xv[i];
                    ball = fminf(ball, v);
                    if ((g_sel[i * 16u + ow0] >> lane) & 1u) b0 = fminf(b0, v);
                    if ((g_sel[i * 16u + ow1] >> lane) & 1u) b1 = fminf(b1, v);
                }
                if (!ok0) r0 = isinf(b0) ? ball + 1.0f : b0;
                if (!ok1) r1 = isinf(b1) ? ball + 1.0f : b1;
            }
        }

        out[bid * OUT_DIM + ow0 * 32u + lane] = r0;   // coalesced
        out[bid * OUT_DIM + ow1 * 32u + lane] = r1;
    }
}

// ---------------------------------------------------------------------------
extern "C" void kernel_launch(void* const* d_in, const int* in_sizes, int n_in,
                              void* d_out, int out_size) {
    const float* x  = (const float*)d_in[0];   // [512, 512]
    const float* pw = (const float*)d_in[1];   // [512, 512, 2]
    float* out      = (float*)d_out;           // [512, 512]

    mask_kernel<<<256, 256>>>(pw);
    gather_kernel<<<B_DIM, 256>>>(x, out);
}

// round 16
// speedup vs baseline: 1.0239x; 1.0030x over previous
#include <cuda_runtime.h>
#include <stdint.h>
#include <math.h>

// ---------------------------------------------------------------------------
// out[b,o] = min_i ( x[b,i] + mask[o,i] ),  B=IN=OUT=512,  x in [0,1)
// mask in {0,1}  =>  out[b,o] = min over SELECTED i of x[b,i]  (sparse min).
// Selection = JAX threefry bernoulli (partitionable variant, validated R2-R15).
// K1: mask (coalesced, ILP4).  K2: parallel filter -> warp0 sort -> gather.
// ---------------------------------------------------------------------------

#define B_DIM   512
#define IN_DIM  512
#define OUT_DIM 512
#define TAU     0.15f

// ROW-major selection bitmask: bit o%32 of g_sel[i*16 + (o>>5)]
__device__ uint32_t g_sel[IN_DIM * 16];

// ---------------- Threefry-2x32 (constexpr) --------------------------------
struct TF2 { uint32_t a, b; };

__host__ __device__ constexpr uint32_t rotl32(uint32_t v, int r) {
    return (v << r) | (v >> (32 - r));
}

__host__ __device__ constexpr TF2 tf2x32(uint32_t k0, uint32_t k1,
                                         uint32_t x0, uint32_t x1) {
    uint32_t k2 = k0 ^ k1 ^ 0x1BD11BDAu;
    x0 += k0; x1 += k1;
    x0 += x1; x1 = rotl32(x1, 13) ^ x0;
    x0 += x1; x1 = rotl32(x1, 15) ^ x0;
    x0 += x1; x1 = rotl32(x1, 26) ^ x0;
    x0 += x1; x1 = rotl32(x1,  6) ^ x0;
    x0 += k1; x1 += k2 + 1u;
    x0 += x1; x1 = rotl32(x1, 17) ^ x0;
    x0 += x1; x1 = rotl32(x1, 29) ^ x0;
    x0 += x1; x1 = rotl32(x1, 16) ^ x0;
    x0 += x1; x1 = rotl32(x1, 24) ^ x0;
    x0 += k2; x1 += k0 + 2u;
    x0 += x1; x1 = rotl32(x1, 13) ^ x0;
    x0 += x1; x1 = rotl32(x1, 15) ^ x0;
    x0 += x1; x1 = rotl32(x1, 26) ^ x0;
    x0 += x1; x1 = rotl32(x1,  6) ^ x0;
    x0 += k0; x1 += k1 + 3u;
    x0 += x1; x1 = rotl32(x1, 17) ^ x0;
    x0 += x1; x1 = rotl32(x1, 29) ^ x0;
    x0 += x1; x1 = rotl32(x1, 16) ^ x0;
    x0 += x1; x1 = rotl32(x1, 24) ^ x0;
    x0 += k1; x1 += k2 + 4u;
    x0 += x1; x1 = rotl32(x1, 13) ^ x0;
    x0 += x1; x1 = rotl32(x1, 15) ^ x0;
    x0 += x1; x1 = rotl32(x1, 26) ^ x0;
    x0 += x1; x1 = rotl32(x1,  6) ^ x0;
    x0 += k2; x1 += k0 + 5u;
    return TF2{x0, x1};
}

constexpr TF2 KB = tf2x32(0u, 42u, 0u, 0u);   // k_bern (foldlike split of key 42)

// ---------------- in-warp bitonic helpers (4 elems/lane, e = 4*lane+c) ------
#define BSWAP(A, PA, KEEPMIN) ((KEEPMIN) ? umin((A),(PA)) : umax((A),(PA)))

#define CE(A, B, ASC) { uint32_t lo_ = umin(A,B), hi_ = umax(A,B);            \
                        A = (ASC) ? lo_ : hi_;  B = (ASC) ? hi_ : lo_; }

#define INTRA(D) { CE(v0, v2, D) CE(v1, v3, D) CE(v0, v1, D) CE(v2, v3, D) }

#define SSTAGE(J4, D) {                                                       \
    uint32_t p0_ = __shfl_xor_sync(0xFFFFFFFFu, v0, J4);                      \
    uint32_t p1_ = __shfl_xor_sync(0xFFFFFFFFu, v1, J4);                      \
    uint32_t p2_ = __shfl_xor_sync(0xFFFFFFFFu, v2, J4);                      \
    uint32_t p3_ = __shfl_xor_sync(0xFFFFFFFFu, v3, J4);                      \
    bool km_ = (D) == ((lane & (J4)) == 0);                                   \
    v0 = BSWAP(v0, p0_, km_); v1 = BSWAP(v1, p1_, km_);                       \
    v2 = BSWAP(v2, p2_, km_); v3 = BSWAP(v3, p3_, km_); }

// 5-step butterfly 32x32 bit-matrix transpose across lanes
#define TSTEP(V, K, M) {                                                      \
    uint32_t y_ = __shfl_xor_sync(0xFFFFFFFFu, V, K);                         \
    V = (lane & (K)) ? ((V & (M)) | ((y_ >> (K)) & ~(M)))                     \
                     : ((V & ~(M)) | ((y_ << (K)) & (M))); }

#define TRANSPOSE32(V) TSTEP(V, 16, 0xFFFF0000u) TSTEP(V, 8, 0xFF00FF00u)     \
                       TSTEP(V, 4,  0xF0F0F0F0u) TSTEP(V, 2, 0xCCCCCCCCu)     \
                       TSTEP(V, 1,  0xAAAAAAAAu)

// ---------------- K1: mask ---------------------------------------------------
// 256 CTAs: CTA = (ow = bid&15, ib = (bid>>4)*32). Staged pw, ILP4 threefry.
__global__ __launch_bounds__(256) void mask_kernel(const float* __restrict__ pw) {
    __shared__ float s_wx[32][33], s_wy[32][33];      // padded: conflict-free

    const int t    = threadIdx.x;
    const int lane = t & 31;
    const uint32_t w  = (uint32_t)t >> 5;             // 0..7
    const uint32_t ow = (uint32_t)blockIdx.x & 15u;
    const uint32_t ib = ((uint32_t)blockIdx.x >> 4) * 32u;

    // stage 32o x 32i pw block (8KB), 256B-contiguous per o-row
    const float2* pwp = reinterpret_cast<const float2*>(pw);
#pragma unroll
    for (int q = 0; q < 4; ++q) {
        int idx = q * 256 + t;                        // 0..1023
        int ol = idx >> 5, ii = idx & 31;
        float2 v = pwp[(ow * 32u + ol) * 512u + ib + ii];
        s_wx[ol][ii] = v.x;
        s_wy[ol][ii] = v.y;
    }
    __syncthreads();

    const uint32_t o = ow * 32u + lane;
    uint32_t iloc[4]; bool s[4];
#pragma unroll
    for (int k = 0; k < 4; ++k) {                     // 4 independent chains
        iloc[k] = w * 4u + k;
        uint32_t n = o * 512u + ib + iloc[k];
        TF2 r = tf2x32(KB.a, KB.b, 0u, n);
        uint32_t bits = r.a ^ r.b;
        float u = __uint_as_float((bits >> 9) | 0x3F800000u) - 1.0f;
        float wx = s_wx[lane][iloc[k]], wy = s_wy[lane][iloc[k]];
        float tt = u * (1.0f + __expf(wx - wy));
        if (tt < 1.0f - 1e-5f)      s[k] = true;
        else if (tt > 1.0f + 1e-5f) s[k] = false;
        else {                                        // boundary: exact fp64
            double e = exp((double)wx - (double)wy);
            s[k] = ((double)u) * (1.0 + e) < 1.0;
        }
    }
#pragma unroll
    for (int k = 0; k < 4; ++k) {
        uint32_t word = __ballot_sync(0xFFFFFFFFu, s[k]);
        if (lane == 0) g_sel[(ib + iloc[k]) * 16u + ow] = word;
    }
}

// ---------------- K2: parallel filter -> warp0 sort -> staged gather --------
__global__ __launch_bounds__(256) void gather_kernel(
    const float* __restrict__ x, float* __restrict__ out) {
    __shared__ uint32_t s_ck[8][64];                  // per-warp candidates
    __shared__ int      s_cnt[8], s_off[8], s_tot, s_Ls;
    __shared__ uint32_t sk[128];                      // compact candidate keys
    __shared__ float    s_xv[512];
    __shared__ uint32_t s_ti[64];
    __shared__ float    s_tv[64];
    __shared__ uint32_t s_m[64][17];                  // staged sel words

    const int t    = threadIdx.x;
    const int bid  = blockIdx.x;
    const int lane = t & 31;
    const uint32_t wrp = (uint32_t)t >> 5;

    // ---- all 8 warps: load + filter their 64 elements (2/lane) ----
    {
        float2 v = reinterpret_cast<const float2*>(x + bid * IN_DIM)[t];
        reinterpret_cast<float2*>(s_xv)[t] = v;
        int idx0 = 2 * t, idx1 = 2 * t + 1;
        int c = 0;
        bool p0 = v.x < TAU;
        uint32_t b0 = __ballot_sync(0xFFFFFFFFu, p0);
        if (p0) s_ck[wrp][__popc(b0 & ((1u << lane) - 1u))] =
                    ((__float_as_uint(v.x) >> 7) << 9) | (uint32_t)idx0;
        c = __popc(b0);
        bool p1 = v.y < TAU;
        uint32_t b1 = __ballot_sync(0xFFFFFFFFu, p1);
        if (p1) s_ck[wrp][c + __popc(b1 & ((1u << lane) - 1u))] =
                    ((__float_as_uint(v.y) >> 7) << 9) | (uint32_t)idx1;
        c += __popc(b1);
        if (lane == 0) s_cnt[wrp] = c;
    }
    __syncthreads();

    if (t == 0) {                                     // tiny scan
        int acc = 0;
#pragma unroll
        for (int w2 = 0; w2 < 8; ++w2) { s_off[w2] = acc; acc += s_cnt[w2]; }
        s_tot = acc;
        s_Ls = (acc > 128) ? 0 : (acc < 64 ? acc : 64);
    }
    __syncthreads();

    {   // compact into sk[0..128) and pad
        const int cnt = s_cnt[wrp], off = s_off[wrp];
        for (int j = lane; j < cnt; j += 32) {
            int d = off + j;
            if (d < 128) sk[d] = s_ck[wrp][j];
        }
        const int tot = s_tot;
        for (int j = t; j < 128; j += 256)
            if (j >= tot) sk[j] = 0xFFFFFFFFu;
    }
    __syncthreads();

    // ---- warp 0: in-warp bitonic sort of 128 (e = 4*lane + c) ----
    if (wrp == 0) {
        uint32_t v0 = sk[4*lane+0], v1 = sk[4*lane+1],
                 v2 = sk[4*lane+2], v3 = sk[4*lane+3];
        CE(v0, v1, true) CE(v2, v3, false)                        // k=2
        { bool d = ((lane & 1) == 0); INTRA(d) }                  // k=4
        { bool d = ((lane & 2) == 0); SSTAGE(1, d) INTRA(d) }     // k=8
        { bool d = ((lane & 4) == 0); SSTAGE(2, d) SSTAGE(1, d) INTRA(d) }
        { bool d = ((lane & 8) == 0);
          SSTAGE(4, d) SSTAGE(2, d) SSTAGE(1, d) INTRA(d) }
        { bool d = ((lane & 16) == 0);
          SSTAGE(8, d) SSTAGE(4, d) SSTAGE(2, d) SSTAGE(1, d) INTRA(d) }
        { const bool d = true;                                    // k=128
          SSTAGE(16, d) SSTAGE(8, d) SSTAGE(4, d) SSTAGE(2, d) SSTAGE(1, d) INTRA(d) }

        if (lane < 16) {                    // sorted elems 0..63
            uint32_t kk[4] = {v0, v1, v2, v3};
#pragma unroll
            for (int c = 0; c < 4; ++c) {
                uint32_t ii = kk[c] & 511u;
                s_ti[4*lane + c] = ii;
                s_tv[4*lane + c] = s_xv[ii];
            }
        }
    }
    __syncthreads();

    // stage sel words for 64 candidates x 16 ow (64B-contiguous loads)
    const int L = s_Ls;
#pragma unroll
    for (int q = 0; q < 4; ++q) {
        int idx = q * 256 + t;                        // 0..1023
        int j = idx >> 4, ow2 = idx & 15;
        s_m[j][ow2] = (j < L) ? g_sel[s_ti[j] * 16u + ow2] : 0u;
    }
    __syncthreads();

    {
        const uint32_t ow0 = wrp, ow1 = wrp + 8u;
        float val = s_tv[lane];
        uint32_t m0 = s_m[lane][ow0];                 // conflict-free (pad 17)
        uint32_t m1 = s_m[lane][ow1];
        TRANSPOSE32(m0)
        TRANSPOSE32(m1)
        bool ok0 = (m0 != 0), ok1 = (m1 != 0);
        float r0 = __shfl_sync(0xFFFFFFFFu, val, ok0 ? (__ffs(m0) - 1) : 0);
        float r1 = __shfl_sync(0xFFFFFFFFu, val, ok1 ? (__ffs(m1) - 1) : 0);

        if (!__all_sync(0xFFFFFFFFu, ok0 && ok1)) {   // rare second round
            float val2 = s_tv[32 + lane];
            uint32_t n0 = s_m[32 + lane][ow0];
            uint32_t n1 = s_m[32 + lane][ow1];
            TRANSPOSE32(n0)
            TRANSPOSE32(n1)
            float q0 = __shfl_sync(0xFFFFFFFFu, val2, n0 ? (__ffs(n0) - 1) : 0);
            float q1 = __shfl_sync(0xFFFFFFFFu, val2, n1 ? (__ffs(n1) - 1) : 0);
            if (!ok0 && n0) { r0 = q0; ok0 = true; }
            if (!ok1 && n1) { r1 = q1; ok1 = true; }

            if (!ok0 || !ok1) {                       // exact dense fallback
                float b0 = INFINITY, b1 = INFINITY, ball = INFINITY;
                for (int i = 0; i < IN_DIM; ++i) {
                    float v = s_xv[i];
                    ball = fminf(ball, v);
                    if ((g_sel[i * 16u + ow0] >> lane) & 1u) b0 = fminf(b0, v);
                    if ((g_sel[i * 16u + ow1] >> lane) & 1u) b1 = fminf(b1, v);
                }
                if (!ok0) r0 = isinf(b0) ? ball + 1.0f : b0;
                if (!ok1) r1 = isinf(b1) ? ball + 1.0f : b1;
            }
        }

        out[bid * OUT_DIM + ow0 * 32u + lane] = r0;   // coalesced
        out[bid * OUT_DIM + ow1 * 32u + lane] = r1;
    }
}

// ---------------------------------------------------------------------------
extern "C" void kernel_launch(void* const* d_in, const int* in_sizes, int n_in,
                              void* d_out, int out_size) {
    const float* x  = (const float*)d_in[0];   // [512, 512]
    const float* pw = (const float*)d_in[1];   // [512, 512, 2]
    float* out      = (float*)d_out;           // [512, 512]

    mask_kernel<<<256, 256>>>(pw);
    gather_kernel<<<B_DIM, 256>>>(x, out);
}